// round 4
// baseline (speedup 1.0000x reference)
#include <cuda_runtime.h>
#include <cuda_bf16.h>
#include <mma.h>
#include <stdint.h>

using namespace nvcuda;

// Problem constants
#define BB 4
#define SS 2048
#define EE 1024
#define HH 16
#define DD 64
#define MTOT (BB*SS)   // 8192
#define SCALING 0.125f

// Scratch (allocation-free rule: __device__ globals)
__device__ float g_q[BB*HH*SS*DD];    // [B,H,S,D]
__device__ float g_k[BB*HH*SS*DD];
__device__ float g_v[BB*HH*SS*DD];
__device__ float g_att[BB*SS*EE];     // [B,S,E]

__device__ __forceinline__ float to_tf32(float x) {
    uint32_t u; asm("cvt.rna.tf32.f32 %0, %1;" : "=r"(u) : "f"(x));
    return __uint_as_float(u);
}

__device__ __forceinline__ void mma_tf32(float* c,
    uint32_t a0, uint32_t a1, uint32_t a2, uint32_t a3,
    uint32_t b0, uint32_t b1)
{
    asm volatile("mma.sync.aligned.m16n8k8.row.col.f32.tf32.tf32.f32 "
        "{%0,%1,%2,%3},{%4,%5,%6,%7},{%8,%9},{%0,%1,%2,%3};\n"
        : "+f"(c[0]), "+f"(c[1]), "+f"(c[2]), "+f"(c[3])
        : "r"(a0), "r"(a1), "r"(a2), "r"(a3), "r"(b0), "r"(b1));
}

// within-8 column permutation: puts cols c and c+4 adjacent (float2 frag loads)
__device__ __forceinline__ int perm8(int c) { return 2 * (c & 3) + ((c >> 2) & 1); }

// ---------------------------------------------------------------------------
// Projection GEMM: C[M,N] = A[M,K] @ W[N,K]^T + bias. bf16 split-3 (hi/lo).
// Split once at smem store (bf16x2 packed). 128x128 tile, BK=32, 256 thr.
// ---------------------------------------------------------------------------
#define PK 32
#define PLB 40      // bf16 row pitch
#define PLDC 132
#define PROJ_SMEM (128*PLDC*4)   // 67584 B; bf16 tiles use first 40960 B

__global__ __launch_bounds__(256, 2)
void proj_kernel(const float* __restrict__ A, const float* __restrict__ W,
                 const float* __restrict__ bias, float* __restrict__ out,
                 float scale, int mode)
{
    extern __shared__ char smraw[];
    __nv_bfloat16* Ahi = (__nv_bfloat16*)smraw;
    __nv_bfloat16* Alo = Ahi + 128 * PLB;
    __nv_bfloat16* Whi = Alo + 128 * PLB;
    __nv_bfloat16* Wlo = Whi + 128 * PLB;
    float* Cs = (float*)smraw;   // epilogue staging aliases the tiles

    const int m0 = blockIdx.y * 128;
    const int n0 = blockIdx.x * 128;
    const int tid = threadIdx.x;
    const int wid = tid >> 5;
    const int wm = wid >> 2;   // 0..1
    const int wn = wid & 3;    // 0..3

    wmma::fragment<wmma::accumulator, 16, 16, 16, float> acc[4][2];
#pragma unroll
    for (int i = 0; i < 4; i++)
#pragma unroll
        for (int j = 0; j < 2; j++) wmma::fill_fragment(acc[i][j], 0.0f);

    const int r = tid >> 3;          // 0..31
    const int c4 = (tid & 7) * 4;    // 0..28

    for (int k0 = 0; k0 < EE; k0 += PK) {
#pragma unroll
        for (int p = 0; p < 4; p++) {
            int row = r + p * 32;
            float4 av = *(const float4*)&A[(size_t)(m0 + row) * EE + k0 + c4];
            float4 wv = *(const float4*)&W[(size_t)(n0 + row) * EE + k0 + c4];
            int o = row * PLB + c4;
            // packed bf16x2 hi/lo split
            __nv_bfloat162 h01 = __float22bfloat162_rn(make_float2(av.x, av.y));
            __nv_bfloat162 h23 = __float22bfloat162_rn(make_float2(av.z, av.w));
            float2 f01 = __bfloat1622float2(h01);
            float2 f23 = __bfloat1622float2(h23);
            __nv_bfloat162 l01 = __float22bfloat162_rn(make_float2(av.x - f01.x, av.y - f01.y));
            __nv_bfloat162 l23 = __float22bfloat162_rn(make_float2(av.z - f23.x, av.w - f23.y));
            *(__nv_bfloat162*)&Ahi[o + 0] = h01;
            *(__nv_bfloat162*)&Ahi[o + 2] = h23;
            *(__nv_bfloat162*)&Alo[o + 0] = l01;
            *(__nv_bfloat162*)&Alo[o + 2] = l23;
            __nv_bfloat162 g01 = __float22bfloat162_rn(make_float2(wv.x, wv.y));
            __nv_bfloat162 g23 = __float22bfloat162_rn(make_float2(wv.z, wv.w));
            float2 e01 = __bfloat1622float2(g01);
            float2 e23 = __bfloat1622float2(g23);
            __nv_bfloat162 m01 = __float22bfloat162_rn(make_float2(wv.x - e01.x, wv.y - e01.y));
            __nv_bfloat162 m23 = __float22bfloat162_rn(make_float2(wv.z - e23.x, wv.w - e23.y));
            *(__nv_bfloat162*)&Whi[o + 0] = g01;
            *(__nv_bfloat162*)&Whi[o + 2] = g23;
            *(__nv_bfloat162*)&Wlo[o + 0] = m01;
            *(__nv_bfloat162*)&Wlo[o + 2] = m23;
        }
        __syncthreads();

#pragma unroll
        for (int kk = 0; kk < PK; kk += 16) {
            wmma::fragment<wmma::matrix_b, 16, 16, 16, __nv_bfloat16, wmma::col_major> bhi[2], blo[2];
#pragma unroll
            for (int j = 0; j < 2; j++) {
                wmma::load_matrix_sync(bhi[j], &Whi[(wn * 32 + j * 16) * PLB + kk], PLB);
                wmma::load_matrix_sync(blo[j], &Wlo[(wn * 32 + j * 16) * PLB + kk], PLB);
            }
#pragma unroll
            for (int i = 0; i < 4; i++) {
                wmma::fragment<wmma::matrix_a, 16, 16, 16, __nv_bfloat16, wmma::row_major> ahi, alo;
                wmma::load_matrix_sync(ahi, &Ahi[(wm * 64 + i * 16) * PLB + kk], PLB);
                wmma::load_matrix_sync(alo, &Alo[(wm * 64 + i * 16) * PLB + kk], PLB);
#pragma unroll
                for (int j = 0; j < 2; j++) {
                    wmma::mma_sync(acc[i][j], ahi, bhi[j], acc[i][j]);
                    wmma::mma_sync(acc[i][j], ahi, blo[j], acc[i][j]);
                    wmma::mma_sync(acc[i][j], alo, bhi[j], acc[i][j]);
                }
            }
        }
        __syncthreads();
    }

#pragma unroll
    for (int i = 0; i < 4; i++)
#pragma unroll
        for (int j = 0; j < 2; j++)
            wmma::store_matrix_sync(&Cs[(wm * 64 + i * 16) * PLDC + wn * 32 + j * 16],
                                    acc[i][j], PLDC, wmma::mem_row_major);
    __syncthreads();

    {
        int cc = (tid & 31) * 4;
        for (int rp = 0; rp < 16; rp++) {
            int row = (tid >> 5) + rp * 8;
            int m = m0 + row;
#pragma unroll
            for (int q = 0; q < 4; q++) {
                int n = n0 + cc + q;
                float v = (Cs[row * PLDC + cc + q] + bias[n]) * scale;
                if (mode == 0) {
                    int b = m >> 11, s = m & 2047;
                    int h = n >> 6, d = n & 63;
                    out[(((size_t)(b * HH + h)) * SS + s) * DD + d] = v;
                } else {
                    out[(size_t)m * EE + n] = v;
                }
            }
        }
    }
}

// ---------------------------------------------------------------------------
// Flash attention v3: 128 threads, 4 warps x 32 q-rows. KT=64 key tile.
// P fed to PV mma directly from score accumulators (no smem round-trip):
// Q,K stored col-permuted (identity k-slot map), V stored UNPERMUTED [d][kt]
// so B slots (cq,cq+4) pick kt (2cq,2cq+1), matching the accumulator layout.
// ---------------------------------------------------------------------------
#define KT 64
#define LDK 70            // pitch (mod 32 = 6 -> conflict-light row-strided STS)
#define NKT (SS/KT)       // 32
#define ATTN_SMEM ((128*LDK + 64*LDK + 64*LDK)*4)  // 71680 B

__global__ __launch_bounds__(128, 3)
void attn_kernel(const float* __restrict__ Q, const float* __restrict__ K,
                 const float* __restrict__ V, float* __restrict__ out)
{
    extern __shared__ float sm[];
    float* Qs = sm;                  // [128][LDK] tf32, cols permuted, pre-scaled
    float* Ks = Qs + 128 * LDK;      // [64][LDK]  tf32, d-cols permuted
    float* Vt = Ks + 64 * LDK;       // [64][LDK]  V transposed [d][kt], UNPERMUTED

    const int tid = threadIdx.x;
    const int w = tid >> 5;          // 0..3
    const int l = tid & 31;
    const int qa = l >> 2;           // 0..7
    const int cq = l & 3;            // 0..3
    const int q0 = blockIdx.x * 128;
    const int bh = blockIdx.y;       // b*H + h
    const size_t base = (size_t)bh * SS * DD;

    // Load Q tile: scale, tf32, permute cols. One row per thread.
    {
        const float* src = &Q[base + (size_t)(q0 + tid) * DD];
        float* dst = &Qs[tid * LDK];
#pragma unroll
        for (int c = 0; c < DD; c += 4) {
            float4 v = *(const float4*)&src[c];
            float vv[4] = {v.x, v.y, v.z, v.w};
#pragma unroll
            for (int e = 0; e < 4; e++) {
                int col = c + e;
                dst[(col & ~7) + perm8(col & 7)] = to_tf32(vv[e] * SCALING);
            }
        }
    }

    float m_[2][2], l_[2][2];
#pragma unroll
    for (int b = 0; b < 2; b++) { m_[b][0] = m_[b][1] = -1e30f; l_[b][0] = l_[b][1] = 0.f; }
    float o_[2][8][4];
#pragma unroll
    for (int b = 0; b < 2; b++)
#pragma unroll
        for (int dg = 0; dg < 8; dg++)
#pragma unroll
            for (int e = 0; e < 4; e++) o_[b][dg][e] = 0.f;

    for (int kt = 0; kt < NKT; kt++) {
        __syncthreads();   // previous tile fully consumed (also orders Qs on iter 0)
        {
            int row = tid >> 1;              // 0..63
            int cb = (tid & 1) * 32;
            int t0 = kt * KT;
            const float* ksrc = &K[base + (size_t)(t0 + row) * DD + cb];
            const float* vsrc = &V[base + (size_t)(t0 + row) * DD + cb];
#pragma unroll
            for (int c = 0; c < 32; c += 4) {
                float4 kv = *(const float4*)&ksrc[c];
                float4 vv = *(const float4*)&vsrc[c];
                float ka[4] = {kv.x, kv.y, kv.z, kv.w};
                float va[4] = {vv.x, vv.y, vv.z, vv.w};
#pragma unroll
                for (int e = 0; e < 4; e++) {
                    int col = cb + c + e;
                    Ks[row * LDK + (col & ~7) + perm8(col & 7)] = to_tf32(ka[e]);
                    Vt[col * LDK + row] = to_tf32(va[e]);
                }
            }
        }
        __syncthreads();

        // ---- scores: 32 q-rows x 64 kt per warp, two 16-row blocks
        float s[2][8][4];
#pragma unroll
        for (int b = 0; b < 2; b++)
#pragma unroll
            for (int ng = 0; ng < 8; ng++) {
                s[b][ng][0] = 0.f; s[b][ng][1] = 0.f; s[b][ng][2] = 0.f; s[b][ng][3] = 0.f;
            }
        const int r0 = w * 32 + qa;
#pragma unroll
        for (int kk = 0; kk < 8; kk++) {
            float2 aA0 = *(float2*)&Qs[(r0)      * LDK + kk * 8 + 2 * cq];
            float2 aB0 = *(float2*)&Qs[(r0 + 8)  * LDK + kk * 8 + 2 * cq];
            float2 aA1 = *(float2*)&Qs[(r0 + 16) * LDK + kk * 8 + 2 * cq];
            float2 aB1 = *(float2*)&Qs[(r0 + 24) * LDK + kk * 8 + 2 * cq];
#pragma unroll
            for (int ng = 0; ng < 8; ng++) {
                float2 bv = *(float2*)&Ks[(ng * 8 + qa) * LDK + kk * 8 + 2 * cq];
                uint32_t b0 = __float_as_uint(bv.x), b1 = __float_as_uint(bv.y);
                mma_tf32(s[0][ng], __float_as_uint(aA0.x), __float_as_uint(aB0.x),
                                   __float_as_uint(aA0.y), __float_as_uint(aB0.y), b0, b1);
                mma_tf32(s[1][ng], __float_as_uint(aA1.x), __float_as_uint(aB1.x),
                                   __float_as_uint(aA1.y), __float_as_uint(aB1.y), b0, b1);
            }
        }

        // ---- online softmax in registers, per block
#pragma unroll
        for (int b = 0; b < 2; b++) {
            float mxa = -1e30f, mxb = -1e30f;
#pragma unroll
            for (int ng = 0; ng < 8; ng++) {
                mxa = fmaxf(mxa, fmaxf(s[b][ng][0], s[b][ng][1]));
                mxb = fmaxf(mxb, fmaxf(s[b][ng][2], s[b][ng][3]));
            }
            mxa = fmaxf(mxa, __shfl_xor_sync(0xffffffffu, mxa, 1));
            mxa = fmaxf(mxa, __shfl_xor_sync(0xffffffffu, mxa, 2));
            mxb = fmaxf(mxb, __shfl_xor_sync(0xffffffffu, mxb, 1));
            mxb = fmaxf(mxb, __shfl_xor_sync(0xffffffffu, mxb, 2));
            float mna = fmaxf(m_[b][0], mxa), mnb = fmaxf(m_[b][1], mxb);
            float suma = 0.f, sumb = 0.f;
#pragma unroll
            for (int ng = 0; ng < 8; ng++) {
                float p0 = to_tf32(__expf(s[b][ng][0] - mna));
                float p1 = to_tf32(__expf(s[b][ng][1] - mna));
                float p2 = to_tf32(__expf(s[b][ng][2] - mnb));
                float p3 = to_tf32(__expf(s[b][ng][3] - mnb));
                suma += p0 + p1;  sumb += p2 + p3;
                s[b][ng][0] = p0; s[b][ng][1] = p1; s[b][ng][2] = p2; s[b][ng][3] = p3;
            }
            suma += __shfl_xor_sync(0xffffffffu, suma, 1);
            suma += __shfl_xor_sync(0xffffffffu, suma, 2);
            sumb += __shfl_xor_sync(0xffffffffu, sumb, 1);
            sumb += __shfl_xor_sync(0xffffffffu, sumb, 2);
            float ala = __expf(m_[b][0] - mna), alb = __expf(m_[b][1] - mnb);
            m_[b][0] = mna; m_[b][1] = mnb;
            l_[b][0] = l_[b][0] * ala + suma;
            l_[b][1] = l_[b][1] * alb + sumb;
#pragma unroll
            for (int dg = 0; dg < 8; dg++) {
                o_[b][dg][0] *= ala; o_[b][dg][1] *= ala;
                o_[b][dg][2] *= alb; o_[b][dg][3] *= alb;
            }
        }

        // ---- PV: O(32x64) += P(32x64) @ V(64x64); P comes straight from s regs
#pragma unroll
        for (int ng = 0; ng < 8; ng++) {
            uint32_t p00 = __float_as_uint(s[0][ng][0]), p01 = __float_as_uint(s[0][ng][1]);
            uint32_t p02 = __float_as_uint(s[0][ng][2]), p03 = __float_as_uint(s[0][ng][3]);
            uint32_t p10 = __float_as_uint(s[1][ng][0]), p11 = __float_as_uint(s[1][ng][1]);
            uint32_t p12 = __float_as_uint(s[1][ng][2]), p13 = __float_as_uint(s[1][ng][3]);
#pragma unroll
            for (int dg = 0; dg < 8; dg++) {
                float2 bv = *(float2*)&Vt[(dg * 8 + qa) * LDK + ng * 8 + 2 * cq];
                uint32_t b0 = __float_as_uint(bv.x), b1 = __float_as_uint(bv.y);
                // A slots: a0=c0 (kt 2cq), a1=c2, a2=c1 (kt 2cq+1), a3=c3
                mma_tf32(o_[0][dg], p00, p02, p01, p03, b0, b1);
                mma_tf32(o_[1][dg], p10, p12, p11, p13, b0, b1);
            }
        }
    }

    // Final: O /= l, write [B,S,E] at column h*64
    {
        int b = bh >> 4, h = bh & 15;
#pragma unroll
        for (int blk = 0; blk < 2; blk++) {
            float inva = 1.0f / l_[blk][0], invb = 1.0f / l_[blk][1];
            int rowa = q0 + w * 32 + blk * 16 + qa;
            int rowb = rowa + 8;
#pragma unroll
            for (int dg = 0; dg < 8; dg++) {
                int col = h * 64 + dg * 8 + 2 * cq;
                float2 va = make_float2(o_[blk][dg][0] * inva, o_[blk][dg][1] * inva);
                float2 vb = make_float2(o_[blk][dg][2] * invb, o_[blk][dg][3] * invb);
                *(float2*)&out[((size_t)b * SS + rowa) * EE + col] = va;
                *(float2*)&out[((size_t)b * SS + rowb) * EE + col] = vb;
            }
        }
    }
}

// ---------------------------------------------------------------------------
extern "C" void kernel_launch(void* const* d_in, const int* in_sizes, int n_in,
                              void* d_out, int out_size)
{
    const float* query = (const float*)d_in[0];
    const float* key   = (const float*)d_in[1];
    const float* value = (const float*)d_in[2];
    const float* q_w   = (const float*)d_in[3];
    const float* q_b   = (const float*)d_in[4];
    const float* k_w   = (const float*)d_in[5];
    const float* k_b   = (const float*)d_in[6];
    const float* v_w   = (const float*)d_in[7];
    const float* v_b   = (const float*)d_in[8];
    const float* out_w = (const float*)d_in[9];
    const float* out_b = (const float*)d_in[10];
    float* out = (float*)d_out;

    float *gq, *gk, *gv, *gatt;
    cudaGetSymbolAddress((void**)&gq, g_q);
    cudaGetSymbolAddress((void**)&gk, g_k);
    cudaGetSymbolAddress((void**)&gv, g_v);
    cudaGetSymbolAddress((void**)&gatt, g_att);

    cudaFuncSetAttribute(proj_kernel, cudaFuncAttributeMaxDynamicSharedMemorySize, PROJ_SMEM);
    cudaFuncSetAttribute(attn_kernel, cudaFuncAttributeMaxDynamicSharedMemorySize, ATTN_SMEM);

    dim3 pgrid(EE / 128, MTOT / 128);  // (8, 64)
    proj_kernel<<<pgrid, 256, PROJ_SMEM>>>(query, q_w, q_b, gq, 1.0f, 0);
    proj_kernel<<<pgrid, 256, PROJ_SMEM>>>(key,   k_w, k_b, gk, 1.0f, 0);
    proj_kernel<<<pgrid, 256, PROJ_SMEM>>>(value, v_w, v_b, gv, 1.0f, 0);

    dim3 agrid(SS / 128, BB * HH);     // (16, 64)
    attn_kernel<<<agrid, 128, ATTN_SMEM>>>(gq, gk, gv, gatt);

    proj_kernel<<<pgrid, 256, PROJ_SMEM>>>(gatt, out_w, out_b, out, 1.0f, 1);
}

// round 5
// speedup vs baseline: 1.3440x; 1.3440x over previous
#include <cuda_runtime.h>
#include <cuda_bf16.h>
#include <mma.h>
#include <stdint.h>

using namespace nvcuda;

// Problem constants
#define BB 4
#define SS 2048
#define EE 1024
#define HH 16
#define DD 64
#define MTOT (BB*SS)   // 8192
#define SCALING 0.125f

// Scratch (allocation-free rule: __device__ globals)
__device__ float g_q[BB*HH*SS*DD];    // [B,H,S,D]
__device__ float g_k[BB*HH*SS*DD];
__device__ float g_v[BB*HH*SS*DD];
__device__ float g_att[BB*SS*EE];     // [B,S,E]
// Pre-split bf16 scratch (reused serially across the 4 projections)
__device__ __nv_bfloat16 g_Ahi[MTOT*EE];
__device__ __nv_bfloat16 g_Alo[MTOT*EE];
__device__ __nv_bfloat16 g_Whi[EE*EE];
__device__ __nv_bfloat16 g_Wlo[EE*EE];

__device__ __forceinline__ float to_tf32(float x) {
    uint32_t u; asm("cvt.rna.tf32.f32 %0, %1;" : "=r"(u) : "f"(x));
    return __uint_as_float(u);
}

__device__ __forceinline__ void mma_tf32(float* c,
    uint32_t a0, uint32_t a1, uint32_t a2, uint32_t a3,
    uint32_t b0, uint32_t b1)
{
    asm volatile("mma.sync.aligned.m16n8k8.row.col.f32.tf32.tf32.f32 "
        "{%0,%1,%2,%3},{%4,%5,%6,%7},{%8,%9},{%0,%1,%2,%3};\n"
        : "+f"(c[0]), "+f"(c[1]), "+f"(c[2]), "+f"(c[3])
        : "r"(a0), "r"(a1), "r"(a2), "r"(a3), "r"(b0), "r"(b1));
}

// within-8 column permutation: puts cols c and c+4 adjacent (float2 frag loads)
__device__ __forceinline__ int perm8(int c) { return 2 * (c & 3) + ((c >> 2) & 1); }

// ---------------------------------------------------------------------------
// Elementwise hi/lo bf16 split: hi = bf16(x), lo = bf16(x - hi)
// ---------------------------------------------------------------------------
__global__ __launch_bounds__(256)
void split_kernel(const float* __restrict__ X,
                  __nv_bfloat16* __restrict__ hi, __nv_bfloat16* __restrict__ lo)
{
    int i = (blockIdx.x * 256 + threadIdx.x) * 4;
    float4 v = *(const float4*)&X[i];
    __nv_bfloat162 h01 = __float22bfloat162_rn(make_float2(v.x, v.y));
    __nv_bfloat162 h23 = __float22bfloat162_rn(make_float2(v.z, v.w));
    float2 f01 = __bfloat1622float2(h01);
    float2 f23 = __bfloat1622float2(h23);
    __nv_bfloat162 l01 = __float22bfloat162_rn(make_float2(v.x - f01.x, v.y - f01.y));
    __nv_bfloat162 l23 = __float22bfloat162_rn(make_float2(v.z - f23.x, v.w - f23.y));
    *(__nv_bfloat162*)&hi[i + 0] = h01;
    *(__nv_bfloat162*)&hi[i + 2] = h23;
    *(__nv_bfloat162*)&lo[i + 0] = l01;
    *(__nv_bfloat162*)&lo[i + 2] = l23;
}

// ---------------------------------------------------------------------------
// Projection GEMM on pre-split bf16: C = Ahi·Whi^T + Ahi·Wlo^T + Alo·Whi^T + b
// 128x128 tile, BK=64, 256 thr = 8 warps (2x4 of 64x32 warp tiles).
// ---------------------------------------------------------------------------
#define PK 64
#define PLB 72      // bf16 row pitch
#define PLDC 132
#define PROJ_SMEM (4*128*PLB*2)   // 73728 B (Cs 67584 aliases)

__global__ __launch_bounds__(256, 2)
void proj_kernel(const __nv_bfloat16* __restrict__ Ahi, const __nv_bfloat16* __restrict__ Alo,
                 const __nv_bfloat16* __restrict__ Whi, const __nv_bfloat16* __restrict__ Wlo,
                 const float* __restrict__ bias, float* __restrict__ out,
                 float scale, int mode)
{
    extern __shared__ char smraw[];
    __nv_bfloat16* As_hi = (__nv_bfloat16*)smraw;
    __nv_bfloat16* As_lo = As_hi + 128 * PLB;
    __nv_bfloat16* Ws_hi = As_lo + 128 * PLB;
    __nv_bfloat16* Ws_lo = Ws_hi + 128 * PLB;
    float* Cs = (float*)smraw;   // epilogue staging aliases the tiles

    const int m0 = blockIdx.y * 128;
    const int n0 = blockIdx.x * 128;
    const int tid = threadIdx.x;
    const int wid = tid >> 5;
    const int wm = wid >> 2;   // 0..1
    const int wn = wid & 3;    // 0..3

    wmma::fragment<wmma::accumulator, 16, 16, 16, float> acc[4][2];
#pragma unroll
    for (int i = 0; i < 4; i++)
#pragma unroll
        for (int j = 0; j < 2; j++) wmma::fill_fragment(acc[i][j], 0.0f);

    const int lrow = tid >> 1;          // 0..127
    const int lcb = (tid & 1) * 32;     // 0 or 32

    for (int k0 = 0; k0 < EE; k0 += PK) {
        {
            size_t ga = (size_t)(m0 + lrow) * EE + k0 + lcb;
            size_t gw = (size_t)(n0 + lrow) * EE + k0 + lcb;
            int o = lrow * PLB + lcb;
#pragma unroll
            for (int jj = 0; jj < 32; jj += 8) {
                *(uint4*)&As_hi[o + jj] = *(const uint4*)&Ahi[ga + jj];
                *(uint4*)&As_lo[o + jj] = *(const uint4*)&Alo[ga + jj];
                *(uint4*)&Ws_hi[o + jj] = *(const uint4*)&Whi[gw + jj];
                *(uint4*)&Ws_lo[o + jj] = *(const uint4*)&Wlo[gw + jj];
            }
        }
        __syncthreads();

#pragma unroll
        for (int kk = 0; kk < PK; kk += 16) {
            wmma::fragment<wmma::matrix_b, 16, 16, 16, __nv_bfloat16, wmma::col_major> bhi[2], blo[2];
#pragma unroll
            for (int j = 0; j < 2; j++) {
                wmma::load_matrix_sync(bhi[j], &Ws_hi[(wn * 32 + j * 16) * PLB + kk], PLB);
                wmma::load_matrix_sync(blo[j], &Ws_lo[(wn * 32 + j * 16) * PLB + kk], PLB);
            }
#pragma unroll
            for (int i = 0; i < 4; i++) {
                wmma::fragment<wmma::matrix_a, 16, 16, 16, __nv_bfloat16, wmma::row_major> ahi, alo;
                wmma::load_matrix_sync(ahi, &As_hi[(wm * 64 + i * 16) * PLB + kk], PLB);
                wmma::load_matrix_sync(alo, &As_lo[(wm * 64 + i * 16) * PLB + kk], PLB);
#pragma unroll
                for (int j = 0; j < 2; j++) {
                    wmma::mma_sync(acc[i][j], ahi, bhi[j], acc[i][j]);
                    wmma::mma_sync(acc[i][j], ahi, blo[j], acc[i][j]);
                    wmma::mma_sync(acc[i][j], alo, bhi[j], acc[i][j]);
                }
            }
        }
        __syncthreads();
    }

#pragma unroll
    for (int i = 0; i < 4; i++)
#pragma unroll
        for (int j = 0; j < 2; j++)
            wmma::store_matrix_sync(&Cs[(wm * 64 + i * 16) * PLDC + wn * 32 + j * 16],
                                    acc[i][j], PLDC, wmma::mem_row_major);
    __syncthreads();

    {
        int cc = (tid & 31) * 4;
        int n = n0 + cc;
        float4 bv = *(const float4*)&bias[n];
        int h = n >> 6, d0 = n & 63;
        for (int rp = 0; rp < 16; rp++) {
            int row = (tid >> 5) + rp * 8;
            int m = m0 + row;
            float4 v = *(float4*)&Cs[row * PLDC + cc];
            v.x = (v.x + bv.x) * scale;
            v.y = (v.y + bv.y) * scale;
            v.z = (v.z + bv.z) * scale;
            v.w = (v.w + bv.w) * scale;
            if (mode == 0) {
                int b = m >> 11, s = m & 2047;
                *(float4*)&out[(((size_t)(b * HH + h)) * SS + s) * DD + d0] = v;
            } else {
                *(float4*)&out[(size_t)m * EE + n] = v;
            }
        }
    }
}

// ---------------------------------------------------------------------------
// Flash attention v4: 256 threads, 8 warps x 16 q-rows (v2 parallelism).
// P fed to PV mma directly from score accumulators (no smem round-trip).
// Q,K stored col-permuted; V stored UNPERMUTED transposed [d][kt] so B slots
// (cq, cq+4) pick kt (2cq, 2cq+1), matching the accumulator k-permutation.
// ---------------------------------------------------------------------------
#define KT 64
#define LDK 70
#define NKT (SS/KT)       // 32
#define ATTN_SMEM ((128*LDK + 64*LDK + 64*LDK)*4)  // 71680 B

__global__ __launch_bounds__(256, 2)
void attn_kernel(const float* __restrict__ Q, const float* __restrict__ K,
                 const float* __restrict__ V, float* __restrict__ out)
{
    extern __shared__ float sm[];
    float* Qs = sm;                  // [128][LDK] tf32, cols permuted, pre-scaled
    float* Ks = Qs + 128 * LDK;      // [64][LDK]  tf32, d-cols permuted
    float* Vt = Ks + 64 * LDK;       // [64][LDK]  V transposed [d][kt], UNPERMUTED

    const int tid = threadIdx.x;
    const int w = tid >> 5;          // 0..7
    const int l = tid & 31;
    const int qa = l >> 2;           // 0..7
    const int cq = l & 3;            // 0..3
    const int q0 = blockIdx.x * 128;
    const int bh = blockIdx.y;       // b*H + h
    const size_t base = (size_t)bh * SS * DD;

    // Load Q tile: scale, tf32, permute cols. 2 threads per row.
    {
        int row = tid >> 1;
        int cb = (tid & 1) * 32;
        const float* src = &Q[base + (size_t)(q0 + row) * DD + cb];
        float* dst = &Qs[row * LDK];
#pragma unroll
        for (int c = 0; c < 32; c += 4) {
            float4 v = *(const float4*)&src[c];
            float vv[4] = {v.x, v.y, v.z, v.w};
#pragma unroll
            for (int e = 0; e < 4; e++) {
                int col = cb + c + e;
                dst[(col & ~7) + perm8(col & 7)] = to_tf32(vv[e] * SCALING);
            }
        }
    }

    float m_[2] = {-1e30f, -1e30f};
    float l_[2] = {0.f, 0.f};
    float o_[8][4];
#pragma unroll
    for (int dg = 0; dg < 8; dg++)
#pragma unroll
        for (int e = 0; e < 4; e++) o_[dg][e] = 0.f;

    for (int kt = 0; kt < NKT; kt++) {
        __syncthreads();   // previous tile fully consumed (also orders Qs on iter 0)
        {
            int row = tid >> 2;              // 0..63
            int cb = (tid & 3) * 16;
            int t0 = kt * KT;
            const float* ksrc = &K[base + (size_t)(t0 + row) * DD + cb];
            const float* vsrc = &V[base + (size_t)(t0 + row) * DD + cb];
#pragma unroll
            for (int c = 0; c < 16; c += 4) {
                float4 kv = *(const float4*)&ksrc[c];
                float4 vv = *(const float4*)&vsrc[c];
                float ka[4] = {kv.x, kv.y, kv.z, kv.w};
                float va[4] = {vv.x, vv.y, vv.z, vv.w};
#pragma unroll
                for (int e = 0; e < 4; e++) {
                    int col = cb + c + e;
                    Ks[row * LDK + (col & ~7) + perm8(col & 7)] = to_tf32(ka[e]);
                    Vt[col * LDK + row] = to_tf32(va[e]);
                }
            }
        }
        __syncthreads();

        // ---- scores: 16 q-rows x 64 kt per warp
        float s[8][4];
#pragma unroll
        for (int ng = 0; ng < 8; ng++) {
            s[ng][0] = 0.f; s[ng][1] = 0.f; s[ng][2] = 0.f; s[ng][3] = 0.f;
        }
        const int r0 = w * 16 + qa;
#pragma unroll
        for (int kk = 0; kk < 8; kk++) {
            float2 aA = *(float2*)&Qs[(r0)     * LDK + kk * 8 + 2 * cq];
            float2 aB = *(float2*)&Qs[(r0 + 8) * LDK + kk * 8 + 2 * cq];
            uint32_t a0 = __float_as_uint(aA.x), a1 = __float_as_uint(aB.x);
            uint32_t a2 = __float_as_uint(aA.y), a3 = __float_as_uint(aB.y);
#pragma unroll
            for (int ng = 0; ng < 8; ng++) {
                float2 bv = *(float2*)&Ks[(ng * 8 + qa) * LDK + kk * 8 + 2 * cq];
                mma_tf32(s[ng], a0, a1, a2, a3,
                         __float_as_uint(bv.x), __float_as_uint(bv.y));
            }
        }

        // ---- online softmax in registers (rows r0, r0+8)
        float mxa = -1e30f, mxb = -1e30f;
#pragma unroll
        for (int ng = 0; ng < 8; ng++) {
            mxa = fmaxf(mxa, fmaxf(s[ng][0], s[ng][1]));
            mxb = fmaxf(mxb, fmaxf(s[ng][2], s[ng][3]));
        }
        mxa = fmaxf(mxa, __shfl_xor_sync(0xffffffffu, mxa, 1));
        mxa = fmaxf(mxa, __shfl_xor_sync(0xffffffffu, mxa, 2));
        mxb = fmaxf(mxb, __shfl_xor_sync(0xffffffffu, mxb, 1));
        mxb = fmaxf(mxb, __shfl_xor_sync(0xffffffffu, mxb, 2));
        float mna = fmaxf(m_[0], mxa), mnb = fmaxf(m_[1], mxb);
        float suma = 0.f, sumb = 0.f;
#pragma unroll
        for (int ng = 0; ng < 8; ng++) {
            float p0 = to_tf32(__expf(s[ng][0] - mna));
            float p1 = to_tf32(__expf(s[ng][1] - mna));
            float p2 = to_tf32(__expf(s[ng][2] - mnb));
            float p3 = to_tf32(__expf(s[ng][3] - mnb));
            suma += p0 + p1;  sumb += p2 + p3;
            s[ng][0] = p0; s[ng][1] = p1; s[ng][2] = p2; s[ng][3] = p3;
        }
        suma += __shfl_xor_sync(0xffffffffu, suma, 1);
        suma += __shfl_xor_sync(0xffffffffu, suma, 2);
        sumb += __shfl_xor_sync(0xffffffffu, sumb, 1);
        sumb += __shfl_xor_sync(0xffffffffu, sumb, 2);
        float ala = __expf(m_[0] - mna), alb = __expf(m_[1] - mnb);
        m_[0] = mna; m_[1] = mnb;
        l_[0] = l_[0] * ala + suma;
        l_[1] = l_[1] * alb + sumb;
#pragma unroll
        for (int dg = 0; dg < 8; dg++) {
            o_[dg][0] *= ala; o_[dg][1] *= ala;
            o_[dg][2] *= alb; o_[dg][3] *= alb;
        }

        // ---- PV: O(16x64) += P(16x64) @ V(64x64); P straight from s regs
        // A slots: a0 = c0 (kt 2cq), a1 = c2, a2 = c1 (kt 2cq+1), a3 = c3
#pragma unroll
        for (int ng = 0; ng < 8; ng++) {
            uint32_t p0 = __float_as_uint(s[ng][0]), p1 = __float_as_uint(s[ng][1]);
            uint32_t p2 = __float_as_uint(s[ng][2]), p3 = __float_as_uint(s[ng][3]);
#pragma unroll
            for (int dg = 0; dg < 8; dg++) {
                float2 bv = *(float2*)&Vt[(dg * 8 + qa) * LDK + ng * 8 + 2 * cq];
                mma_tf32(o_[dg], p0, p2, p1, p3,
                         __float_as_uint(bv.x), __float_as_uint(bv.y));
            }
        }
    }

    // Final: O /= l, write [B,S,E] at column h*64
    {
        int b = bh >> 4, h = bh & 15;
        float inva = 1.0f / l_[0], invb = 1.0f / l_[1];
        int rowa = q0 + w * 16 + qa;
        int rowb = rowa + 8;
#pragma unroll
        for (int dg = 0; dg < 8; dg++) {
            int col = h * 64 + dg * 8 + 2 * cq;
            float2 va = make_float2(o_[dg][0] * inva, o_[dg][1] * inva);
            float2 vb = make_float2(o_[dg][2] * invb, o_[dg][3] * invb);
            *(float2*)&out[((size_t)b * SS + rowa) * EE + col] = va;
            *(float2*)&out[((size_t)b * SS + rowb) * EE + col] = vb;
        }
    }
}

// ---------------------------------------------------------------------------
extern "C" void kernel_launch(void* const* d_in, const int* in_sizes, int n_in,
                              void* d_out, int out_size)
{
    const float* query = (const float*)d_in[0];
    const float* key   = (const float*)d_in[1];
    const float* value = (const float*)d_in[2];
    const float* q_w   = (const float*)d_in[3];
    const float* q_b   = (const float*)d_in[4];
    const float* k_w   = (const float*)d_in[5];
    const float* k_b   = (const float*)d_in[6];
    const float* v_w   = (const float*)d_in[7];
    const float* v_b   = (const float*)d_in[8];
    const float* out_w = (const float*)d_in[9];
    const float* out_b = (const float*)d_in[10];
    float* out = (float*)d_out;

    float *gq, *gk, *gv, *gatt;
    __nv_bfloat16 *ahi, *alo, *whi, *wlo;
    cudaGetSymbolAddress((void**)&gq, g_q);
    cudaGetSymbolAddress((void**)&gk, g_k);
    cudaGetSymbolAddress((void**)&gv, g_v);
    cudaGetSymbolAddress((void**)&gatt, g_att);
    cudaGetSymbolAddress((void**)&ahi, g_Ahi);
    cudaGetSymbolAddress((void**)&alo, g_Alo);
    cudaGetSymbolAddress((void**)&whi, g_Whi);
    cudaGetSymbolAddress((void**)&wlo, g_Wlo);

    cudaFuncSetAttribute(proj_kernel, cudaFuncAttributeMaxDynamicSharedMemorySize, PROJ_SMEM);
    cudaFuncSetAttribute(attn_kernel, cudaFuncAttributeMaxDynamicSharedMemorySize, ATTN_SMEM);

    const int ablk = (MTOT * EE) / (256 * 4);  // 8192
    const int wblk = (EE * EE) / (256 * 4);    // 1024
    dim3 pgrid(EE / 128, MTOT / 128);          // (8, 64)

    // Q projection
    split_kernel<<<ablk, 256>>>(query, ahi, alo);
    split_kernel<<<wblk, 256>>>(q_w, whi, wlo);
    proj_kernel<<<pgrid, 256, PROJ_SMEM>>>(ahi, alo, whi, wlo, q_b, gq, 1.0f, 0);
    // K projection
    split_kernel<<<ablk, 256>>>(key, ahi, alo);
    split_kernel<<<wblk, 256>>>(k_w, whi, wlo);
    proj_kernel<<<pgrid, 256, PROJ_SMEM>>>(ahi, alo, whi, wlo, k_b, gk, 1.0f, 0);
    // V projection
    split_kernel<<<ablk, 256>>>(value, ahi, alo);
    split_kernel<<<wblk, 256>>>(v_w, whi, wlo);
    proj_kernel<<<pgrid, 256, PROJ_SMEM>>>(ahi, alo, whi, wlo, v_b, gv, 1.0f, 0);

    // Attention
    dim3 agrid(SS / 128, BB * HH);             // (16, 64)
    attn_kernel<<<agrid, 256, ATTN_SMEM>>>(gq, gk, gv, gatt);

    // Output projection
    split_kernel<<<ablk, 256>>>(gatt, ahi, alo);
    split_kernel<<<wblk, 256>>>(out_w, whi, wlo);
    proj_kernel<<<pgrid, 256, PROJ_SMEM>>>(ahi, alo, whi, wlo, out_b, out, 1.0f, 1);
}

// round 6
// speedup vs baseline: 1.5594x; 1.1602x over previous
#include <cuda_runtime.h>
#include <cuda_bf16.h>
#include <mma.h>
#include <stdint.h>

using namespace nvcuda;

// Problem constants
#define BB 4
#define SS 2048
#define EE 1024
#define HH 16
#define DD 64
#define MTOT (BB*SS)   // 8192
#define SCALING 0.125f

// Scratch (allocation-free rule: __device__ globals)
__device__ float g_q[BB*HH*SS*DD];    // [B,H,S,D]
__device__ float g_k[BB*HH*SS*DD];
__device__ float g_v[BB*HH*SS*DD];
__device__ float g_att[BB*SS*EE];     // [B,S,E]

__device__ __forceinline__ float to_tf32(float x) {
    uint32_t u; asm("cvt.rna.tf32.f32 %0, %1;" : "=r"(u) : "f"(x));
    return __uint_as_float(u);
}

__device__ __forceinline__ void mma_tf32(float* c,
    uint32_t a0, uint32_t a1, uint32_t a2, uint32_t a3,
    uint32_t b0, uint32_t b1)
{
    asm volatile("mma.sync.aligned.m16n8k8.row.col.f32.tf32.tf32.f32 "
        "{%0,%1,%2,%3},{%4,%5,%6,%7},{%8,%9},{%0,%1,%2,%3};\n"
        : "+f"(c[0]), "+f"(c[1]), "+f"(c[2]), "+f"(c[3])
        : "r"(a0), "r"(a1), "r"(a2), "r"(a3), "r"(b0), "r"(b1));
}

// within-8 column permutation: puts cols c and c+4 adjacent (float2 frag loads)
__device__ __forceinline__ int perm8(int c) { return 2 * (c & 3) + ((c >> 2) & 1); }

// ---------------------------------------------------------------------------
// Projection GEMM: C[M,N] = A[M,K] @ W[N,K]^T + bias. bf16 split-3 (hi/lo).
// Split once at smem store (bf16x2 packed). 128x128 tile, BK=32, 256 thr.
// (Measured-good config: PK=32, PLB=40.)
// ---------------------------------------------------------------------------
#define PK 32
#define PLB 40      // bf16 row pitch
#define PLDC 132
#define PROJ_SMEM (128*PLDC*4)   // 67584 B; bf16 tiles use first 40960 B

__global__ __launch_bounds__(256, 2)
void proj_kernel(const float* __restrict__ A, const float* __restrict__ W,
                 const float* __restrict__ bias, float* __restrict__ out,
                 float scale, int mode)
{
    extern __shared__ char smraw[];
    __nv_bfloat16* Ahi = (__nv_bfloat16*)smraw;
    __nv_bfloat16* Alo = Ahi + 128 * PLB;
    __nv_bfloat16* Whi = Alo + 128 * PLB;
    __nv_bfloat16* Wlo = Whi + 128 * PLB;
    float* Cs = (float*)smraw;   // epilogue staging aliases the tiles

    const int m0 = blockIdx.y * 128;
    const int n0 = blockIdx.x * 128;
    const int tid = threadIdx.x;
    const int wid = tid >> 5;
    const int wm = wid >> 2;   // 0..1
    const int wn = wid & 3;    // 0..3

    wmma::fragment<wmma::accumulator, 16, 16, 16, float> acc[4][2];
#pragma unroll
    for (int i = 0; i < 4; i++)
#pragma unroll
        for (int j = 0; j < 2; j++) wmma::fill_fragment(acc[i][j], 0.0f);

    const int r = tid >> 3;          // 0..31
    const int c4 = (tid & 7) * 4;    // 0..28

    for (int k0 = 0; k0 < EE; k0 += PK) {
#pragma unroll
        for (int p = 0; p < 4; p++) {
            int row = r + p * 32;
            float4 av = *(const float4*)&A[(size_t)(m0 + row) * EE + k0 + c4];
            float4 wv = *(const float4*)&W[(size_t)(n0 + row) * EE + k0 + c4];
            int o = row * PLB + c4;
            __nv_bfloat162 h01 = __float22bfloat162_rn(make_float2(av.x, av.y));
            __nv_bfloat162 h23 = __float22bfloat162_rn(make_float2(av.z, av.w));
            float2 f01 = __bfloat1622float2(h01);
            float2 f23 = __bfloat1622float2(h23);
            __nv_bfloat162 l01 = __float22bfloat162_rn(make_float2(av.x - f01.x, av.y - f01.y));
            __nv_bfloat162 l23 = __float22bfloat162_rn(make_float2(av.z - f23.x, av.w - f23.y));
            *(__nv_bfloat162*)&Ahi[o + 0] = h01;
            *(__nv_bfloat162*)&Ahi[o + 2] = h23;
            *(__nv_bfloat162*)&Alo[o + 0] = l01;
            *(__nv_bfloat162*)&Alo[o + 2] = l23;
            __nv_bfloat162 g01 = __float22bfloat162_rn(make_float2(wv.x, wv.y));
            __nv_bfloat162 g23 = __float22bfloat162_rn(make_float2(wv.z, wv.w));
            float2 e01 = __bfloat1622float2(g01);
            float2 e23 = __bfloat1622float2(g23);
            __nv_bfloat162 m01 = __float22bfloat162_rn(make_float2(wv.x - e01.x, wv.y - e01.y));
            __nv_bfloat162 m23 = __float22bfloat162_rn(make_float2(wv.z - e23.x, wv.w - e23.y));
            *(__nv_bfloat162*)&Whi[o + 0] = g01;
            *(__nv_bfloat162*)&Whi[o + 2] = g23;
            *(__nv_bfloat162*)&Wlo[o + 0] = m01;
            *(__nv_bfloat162*)&Wlo[o + 2] = m23;
        }
        __syncthreads();

#pragma unroll
        for (int kk = 0; kk < PK; kk += 16) {
            wmma::fragment<wmma::matrix_b, 16, 16, 16, __nv_bfloat16, wmma::col_major> bhi[2], blo[2];
#pragma unroll
            for (int j = 0; j < 2; j++) {
                wmma::load_matrix_sync(bhi[j], &Whi[(wn * 32 + j * 16) * PLB + kk], PLB);
                wmma::load_matrix_sync(blo[j], &Wlo[(wn * 32 + j * 16) * PLB + kk], PLB);
            }
#pragma unroll
            for (int i = 0; i < 4; i++) {
                wmma::fragment<wmma::matrix_a, 16, 16, 16, __nv_bfloat16, wmma::row_major> ahi, alo;
                wmma::load_matrix_sync(ahi, &Ahi[(wm * 64 + i * 16) * PLB + kk], PLB);
                wmma::load_matrix_sync(alo, &Alo[(wm * 64 + i * 16) * PLB + kk], PLB);
#pragma unroll
                for (int j = 0; j < 2; j++) {
                    wmma::mma_sync(acc[i][j], ahi, bhi[j], acc[i][j]);
                    wmma::mma_sync(acc[i][j], ahi, blo[j], acc[i][j]);
                    wmma::mma_sync(acc[i][j], alo, bhi[j], acc[i][j]);
                }
            }
        }
        __syncthreads();
    }

#pragma unroll
    for (int i = 0; i < 4; i++)
#pragma unroll
        for (int j = 0; j < 2; j++)
            wmma::store_matrix_sync(&Cs[(wm * 64 + i * 16) * PLDC + wn * 32 + j * 16],
                                    acc[i][j], PLDC, wmma::mem_row_major);
    __syncthreads();

    {
        int cc = (tid & 31) * 4;
        int n = n0 + cc;
        float4 bv = *(const float4*)&bias[n];
        int h = n >> 6, d0 = n & 63;
        for (int rp = 0; rp < 16; rp++) {
            int row = (tid >> 5) + rp * 8;
            int m = m0 + row;
            float4 v = *(float4*)&Cs[row * PLDC + cc];
            v.x = (v.x + bv.x) * scale;
            v.y = (v.y + bv.y) * scale;
            v.z = (v.z + bv.z) * scale;
            v.w = (v.w + bv.w) * scale;
            if (mode == 0) {
                int b = m >> 11, s = m & 2047;
                *(float4*)&out[(((size_t)(b * HH + h)) * SS + s) * DD + d0] = v;
            } else {
                *(float4*)&out[(size_t)m * EE + n] = v;
            }
        }
    }
}

// ---------------------------------------------------------------------------
// Flash attention v4: 256 threads, 8 warps x 16 q-rows (v2 parallelism).
// P fed to PV mma directly from score accumulators (no smem round-trip).
// Q,K stored col-permuted; V stored UNPERMUTED transposed [d][kt] so B slots
// (cq, cq+4) pick kt (2cq, 2cq+1), matching the accumulator k-permutation.
// ---------------------------------------------------------------------------
#define KT 64
#define LDK 70
#define NKT (SS/KT)       // 32
#define ATTN_SMEM ((128*LDK + 64*LDK + 64*LDK)*4)  // 71680 B

__global__ __launch_bounds__(256, 2)
void attn_kernel(const float* __restrict__ Q, const float* __restrict__ K,
                 const float* __restrict__ V, float* __restrict__ out)
{
    extern __shared__ float sm[];
    float* Qs = sm;                  // [128][LDK] tf32, cols permuted, pre-scaled
    float* Ks = Qs + 128 * LDK;      // [64][LDK]  tf32, d-cols permuted
    float* Vt = Ks + 64 * LDK;       // [64][LDK]  V transposed [d][kt], UNPERMUTED

    const int tid = threadIdx.x;
    const int w = tid >> 5;          // 0..7
    const int l = tid & 31;
    const int qa = l >> 2;           // 0..7
    const int cq = l & 3;            // 0..3
    const int q0 = blockIdx.x * 128;
    const int bh = blockIdx.y;       // b*H + h
    const size_t base = (size_t)bh * SS * DD;

    // Load Q tile: scale, tf32, permute cols. 2 threads per row.
    {
        int row = tid >> 1;
        int cb = (tid & 1) * 32;
        const float* src = &Q[base + (size_t)(q0 + row) * DD + cb];
        float* dst = &Qs[row * LDK];
#pragma unroll
        for (int c = 0; c < 32; c += 4) {
            float4 v = *(const float4*)&src[c];
            float vv[4] = {v.x, v.y, v.z, v.w};
#pragma unroll
            for (int e = 0; e < 4; e++) {
                int col = cb + c + e;
                dst[(col & ~7) + perm8(col & 7)] = to_tf32(vv[e] * SCALING);
            }
        }
    }

    float m_[2] = {-1e30f, -1e30f};
    float l_[2] = {0.f, 0.f};
    float o_[8][4];
#pragma unroll
    for (int dg = 0; dg < 8; dg++)
#pragma unroll
        for (int e = 0; e < 4; e++) o_[dg][e] = 0.f;

    for (int kt = 0; kt < NKT; kt++) {
        __syncthreads();   // previous tile fully consumed (also orders Qs on iter 0)
        {
            int row = tid >> 2;              // 0..63
            int cb = (tid & 3) * 16;
            int t0 = kt * KT;
            const float* ksrc = &K[base + (size_t)(t0 + row) * DD + cb];
            const float* vsrc = &V[base + (size_t)(t0 + row) * DD + cb];
#pragma unroll
            for (int c = 0; c < 16; c += 4) {
                float4 kv = *(const float4*)&ksrc[c];
                float4 vv = *(const float4*)&vsrc[c];
                float ka[4] = {kv.x, kv.y, kv.z, kv.w};
                float va[4] = {vv.x, vv.y, vv.z, vv.w};
#pragma unroll
                for (int e = 0; e < 4; e++) {
                    int col = cb + c + e;
                    Ks[row * LDK + (col & ~7) + perm8(col & 7)] = to_tf32(ka[e]);
                    Vt[col * LDK + row] = to_tf32(va[e]);
                }
            }
        }
        __syncthreads();

        // ---- scores: 16 q-rows x 64 kt per warp
        float s[8][4];
#pragma unroll
        for (int ng = 0; ng < 8; ng++) {
            s[ng][0] = 0.f; s[ng][1] = 0.f; s[ng][2] = 0.f; s[ng][3] = 0.f;
        }
        const int r0 = w * 16 + qa;
#pragma unroll
        for (int kk = 0; kk < 8; kk++) {
            float2 aA = *(float2*)&Qs[(r0)     * LDK + kk * 8 + 2 * cq];
            float2 aB = *(float2*)&Qs[(r0 + 8) * LDK + kk * 8 + 2 * cq];
            uint32_t a0 = __float_as_uint(aA.x), a1 = __float_as_uint(aB.x);
            uint32_t a2 = __float_as_uint(aA.y), a3 = __float_as_uint(aB.y);
#pragma unroll
            for (int ng = 0; ng < 8; ng++) {
                float2 bv = *(float2*)&Ks[(ng * 8 + qa) * LDK + kk * 8 + 2 * cq];
                mma_tf32(s[ng], a0, a1, a2, a3,
                         __float_as_uint(bv.x), __float_as_uint(bv.y));
            }
        }

        // ---- online softmax in registers (rows r0, r0+8)
        float mxa = -1e30f, mxb = -1e30f;
#pragma unroll
        for (int ng = 0; ng < 8; ng++) {
            mxa = fmaxf(mxa, fmaxf(s[ng][0], s[ng][1]));
            mxb = fmaxf(mxb, fmaxf(s[ng][2], s[ng][3]));
        }
        mxa = fmaxf(mxa, __shfl_xor_sync(0xffffffffu, mxa, 1));
        mxa = fmaxf(mxa, __shfl_xor_sync(0xffffffffu, mxa, 2));
        mxb = fmaxf(mxb, __shfl_xor_sync(0xffffffffu, mxb, 1));
        mxb = fmaxf(mxb, __shfl_xor_sync(0xffffffffu, mxb, 2));
        float mna = fmaxf(m_[0], mxa), mnb = fmaxf(m_[1], mxb);
        float suma = 0.f, sumb = 0.f;
#pragma unroll
        for (int ng = 0; ng < 8; ng++) {
            float p0 = to_tf32(__expf(s[ng][0] - mna));
            float p1 = to_tf32(__expf(s[ng][1] - mna));
            float p2 = to_tf32(__expf(s[ng][2] - mnb));
            float p3 = to_tf32(__expf(s[ng][3] - mnb));
            suma += p0 + p1;  sumb += p2 + p3;
            s[ng][0] = p0; s[ng][1] = p1; s[ng][2] = p2; s[ng][3] = p3;
        }
        suma += __shfl_xor_sync(0xffffffffu, suma, 1);
        suma += __shfl_xor_sync(0xffffffffu, suma, 2);
        sumb += __shfl_xor_sync(0xffffffffu, sumb, 1);
        sumb += __shfl_xor_sync(0xffffffffu, sumb, 2);
        float ala = __expf(m_[0] - mna), alb = __expf(m_[1] - mnb);
        m_[0] = mna; m_[1] = mnb;
        l_[0] = l_[0] * ala + suma;
        l_[1] = l_[1] * alb + sumb;
#pragma unroll
        for (int dg = 0; dg < 8; dg++) {
            o_[dg][0] *= ala; o_[dg][1] *= ala;
            o_[dg][2] *= alb; o_[dg][3] *= alb;
        }

        // ---- PV: O(16x64) += P(16x64) @ V(64x64); P straight from s regs
        // A slots: a0 = c0 (kt 2cq), a1 = c2, a2 = c1 (kt 2cq+1), a3 = c3
#pragma unroll
        for (int ng = 0; ng < 8; ng++) {
            uint32_t p0 = __float_as_uint(s[ng][0]), p1 = __float_as_uint(s[ng][1]);
            uint32_t p2 = __float_as_uint(s[ng][2]), p3 = __float_as_uint(s[ng][3]);
#pragma unroll
            for (int dg = 0; dg < 8; dg++) {
                float2 bv = *(float2*)&Vt[(dg * 8 + qa) * LDK + ng * 8 + 2 * cq];
                mma_tf32(o_[dg], p0, p2, p1, p3,
                         __float_as_uint(bv.x), __float_as_uint(bv.y));
            }
        }
    }

    // Final: O /= l, write [B,S,E] at column h*64
    {
        int b = bh >> 4, h = bh & 15;
        float inva = 1.0f / l_[0], invb = 1.0f / l_[1];
        int rowa = q0 + w * 16 + qa;
        int rowb = rowa + 8;
#pragma unroll
        for (int dg = 0; dg < 8; dg++) {
            int col = h * 64 + dg * 8 + 2 * cq;
            float2 va = make_float2(o_[dg][0] * inva, o_[dg][1] * inva);
            float2 vb = make_float2(o_[dg][2] * invb, o_[dg][3] * invb);
            *(float2*)&out[((size_t)b * SS + rowa) * EE + col] = va;
            *(float2*)&out[((size_t)b * SS + rowb) * EE + col] = vb;
        }
    }
}

// ---------------------------------------------------------------------------
extern "C" void kernel_launch(void* const* d_in, const int* in_sizes, int n_in,
                              void* d_out, int out_size)
{
    const float* query = (const float*)d_in[0];
    const float* key   = (const float*)d_in[1];
    const float* value = (const float*)d_in[2];
    const float* q_w   = (const float*)d_in[3];
    const float* q_b   = (const float*)d_in[4];
    const float* k_w   = (const float*)d_in[5];
    const float* k_b   = (const float*)d_in[6];
    const float* v_w   = (const float*)d_in[7];
    const float* v_b   = (const float*)d_in[8];
    const float* out_w = (const float*)d_in[9];
    const float* out_b = (const float*)d_in[10];
    float* out = (float*)d_out;

    float *gq, *gk, *gv, *gatt;
    cudaGetSymbolAddress((void**)&gq, g_q);
    cudaGetSymbolAddress((void**)&gk, g_k);
    cudaGetSymbolAddress((void**)&gv, g_v);
    cudaGetSymbolAddress((void**)&gatt, g_att);

    cudaFuncSetAttribute(proj_kernel, cudaFuncAttributeMaxDynamicSharedMemorySize, PROJ_SMEM);
    cudaFuncSetAttribute(attn_kernel, cudaFuncAttributeMaxDynamicSharedMemorySize, ATTN_SMEM);

    dim3 pgrid(EE / 128, MTOT / 128);  // (8, 64)
    proj_kernel<<<pgrid, 256, PROJ_SMEM>>>(query, q_w, q_b, gq, 1.0f, 0);
    proj_kernel<<<pgrid, 256, PROJ_SMEM>>>(key,   k_w, k_b, gk, 1.0f, 0);
    proj_kernel<<<pgrid, 256, PROJ_SMEM>>>(value, v_w, v_b, gv, 1.0f, 0);

    dim3 agrid(SS / 128, BB * HH);     // (16, 64)
    attn_kernel<<<agrid, 256, ATTN_SMEM>>>(gq, gk, gv, gatt);

    proj_kernel<<<pgrid, 256, PROJ_SMEM>>>(gatt, out_w, out_b, out, 1.0f, 1);
}

// round 10
// speedup vs baseline: 1.7022x; 1.0916x over previous
#include <cuda_runtime.h>
#include <cuda_bf16.h>
#include <mma.h>
#include <stdint.h>

using namespace nvcuda;

// Problem constants
#define BB 4
#define SS 2048
#define EE 1024
#define HH 16
#define DD 64
#define MTOT (BB*SS)   // 8192
#define SCALING 0.125f

// Scratch (allocation-free rule: __device__ globals)
__device__ float g_q[BB*HH*SS*DD];    // [B,H,S,D]
__device__ float g_k[BB*HH*SS*DD];
__device__ float g_v[BB*HH*SS*DD];
__device__ float g_att[BB*SS*EE];     // [B,S,E]

__device__ __forceinline__ float to_tf32(float x) {
    uint32_t u; asm("cvt.rna.tf32.f32 %0, %1;" : "=r"(u) : "f"(x));
    return __uint_as_float(u);
}

__device__ __forceinline__ void mma_tf32(float* c,
    uint32_t a0, uint32_t a1, uint32_t a2, uint32_t a3,
    uint32_t b0, uint32_t b1)
{
    asm volatile("mma.sync.aligned.m16n8k8.row.col.f32.tf32.tf32.f32 "
        "{%0,%1,%2,%3},{%4,%5,%6,%7},{%8,%9},{%0,%1,%2,%3};\n"
        : "+f"(c[0]), "+f"(c[1]), "+f"(c[2]), "+f"(c[3])
        : "r"(a0), "r"(a1), "r"(a2), "r"(a3), "r"(b0), "r"(b1));
}

// within-8 column permutation: puts cols c and c+4 adjacent (float2 frag loads)
__device__ __forceinline__ int perm8(int c) { return 2 * (c & 3) + ((c >> 2) & 1); }

// ---------------------------------------------------------------------------
// Projection GEMM: C[M,N] = A[M,K] @ W[N,K]^T + bias. bf16 split-3 (hi/lo).
// Split once at smem store (bf16x2 packed). 128x128 tile, BK=32, 256 thr.
// (Measured-good config: PK=32, PLB=40.)
// ---------------------------------------------------------------------------
#define PK 32
#define PLB 40      // bf16 row pitch
#define PLDC 132
#define PROJ_SMEM (128*PLDC*4)   // 67584 B; bf16 tiles use first 40960 B

__global__ __launch_bounds__(256, 2)
void proj_kernel(const float* __restrict__ A, const float* __restrict__ W,
                 const float* __restrict__ bias, float* __restrict__ out,
                 float scale, int mode)
{
    extern __shared__ char smraw[];
    __nv_bfloat16* Ahi = (__nv_bfloat16*)smraw;
    __nv_bfloat16* Alo = Ahi + 128 * PLB;
    __nv_bfloat16* Whi = Alo + 128 * PLB;
    __nv_bfloat16* Wlo = Whi + 128 * PLB;
    float* Cs = (float*)smraw;   // epilogue staging aliases the tiles

    const int m0 = blockIdx.y * 128;
    const int n0 = blockIdx.x * 128;
    const int tid = threadIdx.x;
    const int wid = tid >> 5;
    const int wm = wid >> 2;   // 0..1
    const int wn = wid & 3;    // 0..3

    wmma::fragment<wmma::accumulator, 16, 16, 16, float> acc[4][2];
#pragma unroll
    for (int i = 0; i < 4; i++)
#pragma unroll
        for (int j = 0; j < 2; j++) wmma::fill_fragment(acc[i][j], 0.0f);

    const int r = tid >> 3;          // 0..31
    const int c4 = (tid & 7) * 4;    // 0..28

    for (int k0 = 0; k0 < EE; k0 += PK) {
#pragma unroll
        for (int p = 0; p < 4; p++) {
            int row = r + p * 32;
            float4 av = *(const float4*)&A[(size_t)(m0 + row) * EE + k0 + c4];
            float4 wv = *(const float4*)&W[(size_t)(n0 + row) * EE + k0 + c4];
            int o = row * PLB + c4;
            __nv_bfloat162 h01 = __float22bfloat162_rn(make_float2(av.x, av.y));
            __nv_bfloat162 h23 = __float22bfloat162_rn(make_float2(av.z, av.w));
            float2 f01 = __bfloat1622float2(h01);
            float2 f23 = __bfloat1622float2(h23);
            __nv_bfloat162 l01 = __float22bfloat162_rn(make_float2(av.x - f01.x, av.y - f01.y));
            __nv_bfloat162 l23 = __float22bfloat162_rn(make_float2(av.z - f23.x, av.w - f23.y));
            *(__nv_bfloat162*)&Ahi[o + 0] = h01;
            *(__nv_bfloat162*)&Ahi[o + 2] = h23;
            *(__nv_bfloat162*)&Alo[o + 0] = l01;
            *(__nv_bfloat162*)&Alo[o + 2] = l23;
            __nv_bfloat162 g01 = __float22bfloat162_rn(make_float2(wv.x, wv.y));
            __nv_bfloat162 g23 = __float22bfloat162_rn(make_float2(wv.z, wv.w));
            float2 e01 = __bfloat1622float2(g01);
            float2 e23 = __bfloat1622float2(g23);
            __nv_bfloat162 m01 = __float22bfloat162_rn(make_float2(wv.x - e01.x, wv.y - e01.y));
            __nv_bfloat162 m23 = __float22bfloat162_rn(make_float2(wv.z - e23.x, wv.w - e23.y));
            *(__nv_bfloat162*)&Whi[o + 0] = g01;
            *(__nv_bfloat162*)&Whi[o + 2] = g23;
            *(__nv_bfloat162*)&Wlo[o + 0] = m01;
            *(__nv_bfloat162*)&Wlo[o + 2] = m23;
        }
        __syncthreads();

#pragma unroll
        for (int kk = 0; kk < PK; kk += 16) {
            wmma::fragment<wmma::matrix_b, 16, 16, 16, __nv_bfloat16, wmma::col_major> bhi[2], blo[2];
#pragma unroll
            for (int j = 0; j < 2; j++) {
                wmma::load_matrix_sync(bhi[j], &Whi[(wn * 32 + j * 16) * PLB + kk], PLB);
                wmma::load_matrix_sync(blo[j], &Wlo[(wn * 32 + j * 16) * PLB + kk], PLB);
            }
#pragma unroll
            for (int i = 0; i < 4; i++) {
                wmma::fragment<wmma::matrix_a, 16, 16, 16, __nv_bfloat16, wmma::row_major> ahi, alo;
                wmma::load_matrix_sync(ahi, &Ahi[(wm * 64 + i * 16) * PLB + kk], PLB);
                wmma::load_matrix_sync(alo, &Alo[(wm * 64 + i * 16) * PLB + kk], PLB);
#pragma unroll
                for (int j = 0; j < 2; j++) {
                    wmma::mma_sync(acc[i][j], ahi, bhi[j], acc[i][j]);
                    wmma::mma_sync(acc[i][j], ahi, blo[j], acc[i][j]);
                    wmma::mma_sync(acc[i][j], alo, bhi[j], acc[i][j]);
                }
            }
        }
        __syncthreads();
    }

#pragma unroll
    for (int i = 0; i < 4; i++)
#pragma unroll
        for (int j = 0; j < 2; j++)
            wmma::store_matrix_sync(&Cs[(wm * 64 + i * 16) * PLDC + wn * 32 + j * 16],
                                    acc[i][j], PLDC, wmma::mem_row_major);
    __syncthreads();

    {
        int cc = (tid & 31) * 4;
        int n = n0 + cc;
        float4 bv = *(const float4*)&bias[n];
        int h = n >> 6, d0 = n & 63;
        for (int rp = 0; rp < 16; rp++) {
            int row = (tid >> 5) + rp * 8;
            int m = m0 + row;
            float4 v = *(float4*)&Cs[row * PLDC + cc];
            v.x = (v.x + bv.x) * scale;
            v.y = (v.y + bv.y) * scale;
            v.z = (v.z + bv.z) * scale;
            v.w = (v.w + bv.w) * scale;
            if (mode == 0) {
                int b = m >> 11, s = m & 2047;
                *(float4*)&out[(((size_t)(b * HH + h)) * SS + s) * DD + d0] = v;
            } else {
                *(float4*)&out[(size_t)m * EE + n] = v;
            }
        }
    }
}

// ---------------------------------------------------------------------------
// Flash attention v5: v4 + LDK=72 (mod 32 = 8 -> conflict-free fragment LDS.64:
// bank = qa*8 + 2cq enumerates 0,2,..,30 exactly once per 16-lane phase).
// 256 threads, 8 warps x 16 q-rows, register-resident P -> PV.
// ---------------------------------------------------------------------------
#define KT 64
#define LDK 72
#define NKT (SS/KT)       // 32
#define ATTN_SMEM ((128*LDK + 64*LDK + 64*LDK)*4)  // 73728 B

__global__ __launch_bounds__(256, 2)
void attn_kernel(const float* __restrict__ Q, const float* __restrict__ K,
                 const float* __restrict__ V, float* __restrict__ out)
{
    extern __shared__ float sm[];
    float* Qs = sm;                  // [128][LDK] tf32, cols permuted, pre-scaled
    float* Ks = Qs + 128 * LDK;      // [64][LDK]  tf32, d-cols permuted
    float* Vt = Ks + 64 * LDK;       // [64][LDK]  V transposed [d][kt], UNPERMUTED

    const int tid = threadIdx.x;
    const int w = tid >> 5;          // 0..7
    const int l = tid & 31;
    const int qa = l >> 2;           // 0..7
    const int cq = l & 3;            // 0..3
    const int q0 = blockIdx.x * 128;
    const int bh = blockIdx.y;       // b*H + h
    const size_t base = (size_t)bh * SS * DD;

    // Load Q tile: scale, tf32, permute cols. 2 threads per row.
    {
        int row = tid >> 1;
        int cb = (tid & 1) * 32;
        const float* src = &Q[base + (size_t)(q0 + row) * DD + cb];
        float* dst = &Qs[row * LDK];
#pragma unroll
        for (int c = 0; c < 32; c += 4) {
            float4 v = *(const float4*)&src[c];
            float vv[4] = {v.x, v.y, v.z, v.w};
#pragma unroll
            for (int e = 0; e < 4; e++) {
                int col = cb + c + e;
                dst[(col & ~7) + perm8(col & 7)] = to_tf32(vv[e] * SCALING);
            }
        }
    }

    float m_[2] = {-1e30f, -1e30f};
    float l_[2] = {0.f, 0.f};
    float o_[8][4];
#pragma unroll
    for (int dg = 0; dg < 8; dg++)
#pragma unroll
        for (int e = 0; e < 4; e++) o_[dg][e] = 0.f;

    for (int kt = 0; kt < NKT; kt++) {
        __syncthreads();   // previous tile fully consumed (also orders Qs on iter 0)
        {
            int row = tid >> 2;              // 0..63
            int cb = (tid & 3) * 16;
            int t0 = kt * KT;
            const float* ksrc = &K[base + (size_t)(t0 + row) * DD + cb];
            const float* vsrc = &V[base + (size_t)(t0 + row) * DD + cb];
#pragma unroll
            for (int c = 0; c < 16; c += 4) {
                float4 kv = *(const float4*)&ksrc[c];
                float4 vv = *(const float4*)&vsrc[c];
                float ka[4] = {kv.x, kv.y, kv.z, kv.w};
                float va[4] = {vv.x, vv.y, vv.z, vv.w};
#pragma unroll
                for (int e = 0; e < 4; e++) {
                    int col = cb + c + e;
                    Ks[row * LDK + (col & ~7) + perm8(col & 7)] = to_tf32(ka[e]);
                    Vt[col * LDK + row] = to_tf32(va[e]);
                }
            }
        }
        __syncthreads();

        // ---- scores: 16 q-rows x 64 kt per warp
        float s[8][4];
#pragma unroll
        for (int ng = 0; ng < 8; ng++) {
            s[ng][0] = 0.f; s[ng][1] = 0.f; s[ng][2] = 0.f; s[ng][3] = 0.f;
        }
        const int r0 = w * 16 + qa;
#pragma unroll
        for (int kk = 0; kk < 8; kk++) {
            float2 aA = *(float2*)&Qs[(r0)     * LDK + kk * 8 + 2 * cq];
            float2 aB = *(float2*)&Qs[(r0 + 8) * LDK + kk * 8 + 2 * cq];
            uint32_t a0 = __float_as_uint(aA.x), a1 = __float_as_uint(aB.x);
            uint32_t a2 = __float_as_uint(aA.y), a3 = __float_as_uint(aB.y);
#pragma unroll
            for (int ng = 0; ng < 8; ng++) {
                float2 bv = *(float2*)&Ks[(ng * 8 + qa) * LDK + kk * 8 + 2 * cq];
                mma_tf32(s[ng], a0, a1, a2, a3,
                         __float_as_uint(bv.x), __float_as_uint(bv.y));
            }
        }

        // ---- online softmax in registers (rows r0, r0+8)
        float mxa = -1e30f, mxb = -1e30f;
#pragma unroll
        for (int ng = 0; ng < 8; ng++) {
            mxa = fmaxf(mxa, fmaxf(s[ng][0], s[ng][1]));
            mxb = fmaxf(mxb, fmaxf(s[ng][2], s[ng][3]));
        }
        mxa = fmaxf(mxa, __shfl_xor_sync(0xffffffffu, mxa, 1));
        mxa = fmaxf(mxa, __shfl_xor_sync(0xffffffffu, mxa, 2));
        mxb = fmaxf(mxb, __shfl_xor_sync(0xffffffffu, mxb, 1));
        mxb = fmaxf(mxb, __shfl_xor_sync(0xffffffffu, mxb, 2));
        float mna = fmaxf(m_[0], mxa), mnb = fmaxf(m_[1], mxb);
        float suma = 0.f, sumb = 0.f;
#pragma unroll
        for (int ng = 0; ng < 8; ng++) {
            float p0 = to_tf32(__expf(s[ng][0] - mna));
            float p1 = to_tf32(__expf(s[ng][1] - mna));
            float p2 = to_tf32(__expf(s[ng][2] - mnb));
            float p3 = to_tf32(__expf(s[ng][3] - mnb));
            suma += p0 + p1;  sumb += p2 + p3;
            s[ng][0] = p0; s[ng][1] = p1; s[ng][2] = p2; s[ng][3] = p3;
        }
        suma += __shfl_xor_sync(0xffffffffu, suma, 1);
        suma += __shfl_xor_sync(0xffffffffu, suma, 2);
        sumb += __shfl_xor_sync(0xffffffffu, sumb, 1);
        sumb += __shfl_xor_sync(0xffffffffu, sumb, 2);
        float ala = __expf(m_[0] - mna), alb = __expf(m_[1] - mnb);
        m_[0] = mna; m_[1] = mnb;
        l_[0] = l_[0] * ala + suma;
        l_[1] = l_[1] * alb + sumb;
#pragma unroll
        for (int dg = 0; dg < 8; dg++) {
            o_[dg][0] *= ala; o_[dg][1] *= ala;
            o_[dg][2] *= alb; o_[dg][3] *= alb;
        }

        // ---- PV: O(16x64) += P(16x64) @ V(64x64); P straight from s regs
        // A slots: a0 = c0 (kt 2cq), a1 = c2, a2 = c1 (kt 2cq+1), a3 = c3
#pragma unroll
        for (int ng = 0; ng < 8; ng++) {
            uint32_t p0 = __float_as_uint(s[ng][0]), p1 = __float_as_uint(s[ng][1]);
            uint32_t p2 = __float_as_uint(s[ng][2]), p3 = __float_as_uint(s[ng][3]);
#pragma unroll
            for (int dg = 0; dg < 8; dg++) {
                float2 bv = *(float2*)&Vt[(dg * 8 + qa) * LDK + ng * 8 + 2 * cq];
                mma_tf32(o_[dg], p0, p2, p1, p3,
                         __float_as_uint(bv.x), __float_as_uint(bv.y));
            }
        }
    }

    // Final: O /= l, write [B,S,E] at column h*64
    {
        int b = bh >> 4, h = bh & 15;
        float inva = 1.0f / l_[0], invb = 1.0f / l_[1];
        int rowa = q0 + w * 16 + qa;
        int rowb = rowa + 8;
#pragma unroll
        for (int dg = 0; dg < 8; dg++) {
            int col = h * 64 + dg * 8 + 2 * cq;
            float2 va = make_float2(o_[dg][0] * inva, o_[dg][1] * inva);
            float2 vb = make_float2(o_[dg][2] * invb, o_[dg][3] * invb);
            *(float2*)&out[((size_t)b * SS + rowa) * EE + col] = va;
            *(float2*)&out[((size_t)b * SS + rowb) * EE + col] = vb;
        }
    }
}

// ---------------------------------------------------------------------------
extern "C" void kernel_launch(void* const* d_in, const int* in_sizes, int n_in,
                              void* d_out, int out_size)
{
    const float* query = (const float*)d_in[0];
    const float* key   = (const float*)d_in[1];
    const float* value = (const float*)d_in[2];
    const float* q_w   = (const float*)d_in[3];
    const float* q_b   = (const float*)d_in[4];
    const float* k_w   = (const float*)d_in[5];
    const float* k_b   = (const float*)d_in[6];
    const float* v_w   = (const float*)d_in[7];
    const float* v_b   = (const float*)d_in[8];
    const float* out_w = (const float*)d_in[9];
    const float* out_b = (const float*)d_in[10];
    float* out = (float*)d_out;

    float *gq, *gk, *gv, *gatt;
    cudaGetSymbolAddress((void**)&gq, g_q);
    cudaGetSymbolAddress((void**)&gk, g_k);
    cudaGetSymbolAddress((void**)&gv, g_v);
    cudaGetSymbolAddress((void**)&gatt, g_att);

    cudaFuncSetAttribute(proj_kernel, cudaFuncAttributeMaxDynamicSharedMemorySize, PROJ_SMEM);
    cudaFuncSetAttribute(attn_kernel, cudaFuncAttributeMaxDynamicSharedMemorySize, ATTN_SMEM);

    dim3 pgrid(EE / 128, MTOT / 128);  // (8, 64)
    proj_kernel<<<pgrid, 256, PROJ_SMEM>>>(query, q_w, q_b, gq, 1.0f, 0);
    proj_kernel<<<pgrid, 256, PROJ_SMEM>>>(key,   k_w, k_b, gk, 1.0f, 0);
    proj_kernel<<<pgrid, 256, PROJ_SMEM>>>(value, v_w, v_b, gv, 1.0f, 0);

    dim3 agrid(SS / 128, BB * HH);     // (16, 64)
    attn_kernel<<<agrid, 256, ATTN_SMEM>>>(gq, gk, gv, gatt);

    proj_kernel<<<pgrid, 256, PROJ_SMEM>>>(gatt, out_w, out_b, out, 1.0f, 1);
}

// round 11
// speedup vs baseline: 1.8845x; 1.1071x over previous
#include <cuda_runtime.h>
#include <cuda_bf16.h>
#include <mma.h>
#include <stdint.h>

using namespace nvcuda;

// Problem constants
#define BB 4
#define SS 2048
#define EE 1024
#define HH 16
#define DD 64
#define MTOT (BB*SS)   // 8192
#define SCALING 0.125f

// Scratch (allocation-free rule: __device__ globals)
__device__ float g_q[BB*HH*SS*DD];    // [B,H,S,D]
__device__ float g_k[BB*HH*SS*DD];
__device__ float g_v[BB*HH*SS*DD];
__device__ float g_att[BB*SS*EE];     // [B,S,E]

__device__ __forceinline__ float to_tf32(float x) {
    uint32_t u; asm("cvt.rna.tf32.f32 %0, %1;" : "=r"(u) : "f"(x));
    return __uint_as_float(u);
}

__device__ __forceinline__ void mma_tf32(float* c,
    uint32_t a0, uint32_t a1, uint32_t a2, uint32_t a3,
    uint32_t b0, uint32_t b1)
{
    asm volatile("mma.sync.aligned.m16n8k8.row.col.f32.tf32.tf32.f32 "
        "{%0,%1,%2,%3},{%4,%5,%6,%7},{%8,%9},{%0,%1,%2,%3};\n"
        : "+f"(c[0]), "+f"(c[1]), "+f"(c[2]), "+f"(c[3])
        : "r"(a0), "r"(a1), "r"(a2), "r"(a3), "r"(b0), "r"(b1));
}

// within-8 column permutation: puts cols c and c+4 adjacent (float2 frag loads)
__device__ __forceinline__ int perm8(int c) { return 2 * (c & 3) + ((c >> 2) & 1); }

// ---------------------------------------------------------------------------
// Projection GEMM: C[M,N] = A[M,K] @ W[N,K]^T + bias. bf16 split-3 (hi/lo).
// Split once at smem store (bf16x2 packed). 128x128 tile, BK=32, 256 thr.
// Merged: blockIdx.z selects among up to 3 independent (A,W,b,out) sets.
// ---------------------------------------------------------------------------
#define PK 32
#define PLB 40      // bf16 row pitch
#define PLDC 132
#define PROJ_SMEM (128*PLDC*4)   // 67584 B; bf16 tiles use first 40960 B

__global__ __launch_bounds__(256, 2)
void proj_all(const float* __restrict__ A0, const float* __restrict__ A1, const float* __restrict__ A2,
              const float* __restrict__ W0, const float* __restrict__ W1, const float* __restrict__ W2,
              const float* __restrict__ B0, const float* __restrict__ B1, const float* __restrict__ B2,
              float* __restrict__ O0, float* __restrict__ O1, float* __restrict__ O2,
              int mode)
{
    extern __shared__ char smraw[];
    __nv_bfloat16* Ahi = (__nv_bfloat16*)smraw;
    __nv_bfloat16* Alo = Ahi + 128 * PLB;
    __nv_bfloat16* Whi = Alo + 128 * PLB;
    __nv_bfloat16* Wlo = Whi + 128 * PLB;
    float* Cs = (float*)smraw;   // epilogue staging aliases the tiles

    const int z = blockIdx.z;
    const float* A = (z == 0) ? A0 : (z == 1) ? A1 : A2;
    const float* W = (z == 0) ? W0 : (z == 1) ? W1 : W2;
    const float* bias = (z == 0) ? B0 : (z == 1) ? B1 : B2;
    float* out = (z == 0) ? O0 : (z == 1) ? O1 : O2;

    const int m0 = blockIdx.y * 128;
    const int n0 = blockIdx.x * 128;
    const int tid = threadIdx.x;
    const int wid = tid >> 5;
    const int wm = wid >> 2;   // 0..1
    const int wn = wid & 3;    // 0..3

    wmma::fragment<wmma::accumulator, 16, 16, 16, float> acc[4][2];
#pragma unroll
    for (int i = 0; i < 4; i++)
#pragma unroll
        for (int j = 0; j < 2; j++) wmma::fill_fragment(acc[i][j], 0.0f);

    const int r = tid >> 3;          // 0..31
    const int c4 = (tid & 7) * 4;    // 0..28

    for (int k0 = 0; k0 < EE; k0 += PK) {
#pragma unroll
        for (int p = 0; p < 4; p++) {
            int row = r + p * 32;
            float4 av = *(const float4*)&A[(size_t)(m0 + row) * EE + k0 + c4];
            float4 wv = *(const float4*)&W[(size_t)(n0 + row) * EE + k0 + c4];
            int o = row * PLB + c4;
            __nv_bfloat162 h01 = __float22bfloat162_rn(make_float2(av.x, av.y));
            __nv_bfloat162 h23 = __float22bfloat162_rn(make_float2(av.z, av.w));
            float2 f01 = __bfloat1622float2(h01);
            float2 f23 = __bfloat1622float2(h23);
            __nv_bfloat162 l01 = __float22bfloat162_rn(make_float2(av.x - f01.x, av.y - f01.y));
            __nv_bfloat162 l23 = __float22bfloat162_rn(make_float2(av.z - f23.x, av.w - f23.y));
            *(__nv_bfloat162*)&Ahi[o + 0] = h01;
            *(__nv_bfloat162*)&Ahi[o + 2] = h23;
            *(__nv_bfloat162*)&Alo[o + 0] = l01;
            *(__nv_bfloat162*)&Alo[o + 2] = l23;
            __nv_bfloat162 g01 = __float22bfloat162_rn(make_float2(wv.x, wv.y));
            __nv_bfloat162 g23 = __float22bfloat162_rn(make_float2(wv.z, wv.w));
            float2 e01 = __bfloat1622float2(g01);
            float2 e23 = __bfloat1622float2(g23);
            __nv_bfloat162 m01 = __float22bfloat162_rn(make_float2(wv.x - e01.x, wv.y - e01.y));
            __nv_bfloat162 m23 = __float22bfloat162_rn(make_float2(wv.z - e23.x, wv.w - e23.y));
            *(__nv_bfloat162*)&Whi[o + 0] = g01;
            *(__nv_bfloat162*)&Whi[o + 2] = g23;
            *(__nv_bfloat162*)&Wlo[o + 0] = m01;
            *(__nv_bfloat162*)&Wlo[o + 2] = m23;
        }
        __syncthreads();

#pragma unroll
        for (int kk = 0; kk < PK; kk += 16) {
            wmma::fragment<wmma::matrix_b, 16, 16, 16, __nv_bfloat16, wmma::col_major> bhi[2], blo[2];
#pragma unroll
            for (int j = 0; j < 2; j++) {
                wmma::load_matrix_sync(bhi[j], &Whi[(wn * 32 + j * 16) * PLB + kk], PLB);
                wmma::load_matrix_sync(blo[j], &Wlo[(wn * 32 + j * 16) * PLB + kk], PLB);
            }
#pragma unroll
            for (int i = 0; i < 4; i++) {
                wmma::fragment<wmma::matrix_a, 16, 16, 16, __nv_bfloat16, wmma::row_major> ahi, alo;
                wmma::load_matrix_sync(ahi, &Ahi[(wm * 64 + i * 16) * PLB + kk], PLB);
                wmma::load_matrix_sync(alo, &Alo[(wm * 64 + i * 16) * PLB + kk], PLB);
#pragma unroll
                for (int j = 0; j < 2; j++) {
                    wmma::mma_sync(acc[i][j], ahi, bhi[j], acc[i][j]);
                    wmma::mma_sync(acc[i][j], ahi, blo[j], acc[i][j]);
                    wmma::mma_sync(acc[i][j], alo, bhi[j], acc[i][j]);
                }
            }
        }
        __syncthreads();
    }

#pragma unroll
    for (int i = 0; i < 4; i++)
#pragma unroll
        for (int j = 0; j < 2; j++)
            wmma::store_matrix_sync(&Cs[(wm * 64 + i * 16) * PLDC + wn * 32 + j * 16],
                                    acc[i][j], PLDC, wmma::mem_row_major);
    __syncthreads();

    {
        int cc = (tid & 31) * 4;
        int n = n0 + cc;
        float4 bv = *(const float4*)&bias[n];
        int h = n >> 6, d0 = n & 63;
        for (int rp = 0; rp < 16; rp++) {
            int row = (tid >> 5) + rp * 8;
            int m = m0 + row;
            float4 v = *(float4*)&Cs[row * PLDC + cc];
            v.x += bv.x; v.y += bv.y; v.z += bv.z; v.w += bv.w;
            if (mode == 0) {
                int b = m >> 11, s = m & 2047;
                *(float4*)&out[(((size_t)(b * HH + h)) * SS + s) * DD + d0] = v;
            } else {
                *(float4*)&out[(size_t)m * EE + n] = v;
            }
        }
    }
}

// ---------------------------------------------------------------------------
// Flash attention v6: 256 thr, 8 warps x 16 q-rows, register P -> PV.
// KT=128 fill (two 64-kt compute chunks per fill) halves barrier count.
// Ks stored via interleaved STS.128 pairs (perm8 block = [c0,c4,c1,c5][c2,c6,c3,c7]).
// Vt stored via STS.128 runs along kt (scalar coalesced LDG).
// LDK=72, LDKV=136 (both mod 32 = 8 -> conflict-free fragment LDS.64).
// ---------------------------------------------------------------------------
#define LDK 72
#define LDKV 136
#define ATTN_SMEM ((128*LDK + 128*LDK + 64*LDKV)*4)  // 108544 B

__global__ __launch_bounds__(256, 2)
void attn_kernel(const float* __restrict__ Q, const float* __restrict__ K,
                 const float* __restrict__ V, float* __restrict__ out)
{
    extern __shared__ float sm[];
    float* Qs = sm;                   // [128][LDK]  tf32, cols permuted, pre-scaled
    float* Ks = Qs + 128 * LDK;       // [128][LDK]  tf32, d-cols permuted (128 kt rows)
    float* Vt = Ks + 128 * LDK;       // [64][LDKV]  V transposed [d][kt 0..127]

    const int tid = threadIdx.x;
    const int w = tid >> 5;           // 0..7
    const int l = tid & 31;
    const int qa = l >> 2;            // 0..7
    const int cq = l & 3;             // 0..3
    const int q0 = blockIdx.x * 128;
    const int bh = blockIdx.y;        // b*H + h
    const size_t base = (size_t)bh * SS * DD;

    // Load Q tile: scale, tf32, permute cols. 2 threads per row.
    {
        int row = tid >> 1;
        int cb = (tid & 1) * 32;
        const float* src = &Q[base + (size_t)(q0 + row) * DD + cb];
        float* dst = &Qs[row * LDK + cb];
#pragma unroll
        for (int b = 0; b < 4; b++) {
            float4 x = *(const float4*)&src[b * 8];
            float4 y = *(const float4*)&src[b * 8 + 4];
            float4 v1 = make_float4(to_tf32(x.x * SCALING), to_tf32(y.x * SCALING),
                                    to_tf32(x.y * SCALING), to_tf32(y.y * SCALING));
            float4 v2 = make_float4(to_tf32(x.z * SCALING), to_tf32(y.z * SCALING),
                                    to_tf32(x.w * SCALING), to_tf32(y.w * SCALING));
            *(float4*)&dst[b * 8] = v1;
            *(float4*)&dst[b * 8 + 4] = v2;
        }
    }

    float m_[2] = {-1e30f, -1e30f};
    float l_[2] = {0.f, 0.f};
    float o_[8][4];
#pragma unroll
    for (int dg = 0; dg < 8; dg++)
#pragma unroll
        for (int e = 0; e < 4; e++) o_[dg][e] = 0.f;

    for (int kt = 0; kt < SS / 128; kt++) {     // 16 fills
        __syncthreads();   // previous tile fully consumed (also orders Qs on iter 0)
        const int t0 = kt * 128;
        // ---- K fill: row = kt-in-tile, interleaved-pair float4 stores
        {
            int row = tid >> 1;               // 0..127
            int half = (tid & 1) * 32;
            const float* ksrc = &K[base + (size_t)(t0 + row) * DD + half];
            float* kdst = &Ks[row * LDK + half];
#pragma unroll
            for (int b = 0; b < 4; b++) {
                float4 x = *(const float4*)&ksrc[b * 8];
                float4 y = *(const float4*)&ksrc[b * 8 + 4];
                float4 v1 = make_float4(to_tf32(x.x), to_tf32(y.x), to_tf32(x.y), to_tf32(y.y));
                float4 v2 = make_float4(to_tf32(x.z), to_tf32(y.z), to_tf32(x.w), to_tf32(y.w));
                *(float4*)&kdst[b * 8] = v1;
                *(float4*)&kdst[b * 8 + 4] = v2;
            }
        }
        // ---- V fill: one d-col per thread-slot, float4 runs along kt
        {
            int d = l + 32 * (w & 1);         // 0..63
            int ktq = (w >> 1) * 32;          // 0,32,64,96
            const float* vsrc = &V[base + (size_t)(t0 + ktq) * DD + d];
            float* vdst = &Vt[d * LDKV + ktq];
#pragma unroll
            for (int g = 0; g < 8; g++) {
                float a0 = vsrc[(g * 4 + 0) * DD];
                float a1 = vsrc[(g * 4 + 1) * DD];
                float a2 = vsrc[(g * 4 + 2) * DD];
                float a3 = vsrc[(g * 4 + 3) * DD];
                *(float4*)&vdst[g * 4] =
                    make_float4(to_tf32(a0), to_tf32(a1), to_tf32(a2), to_tf32(a3));
            }
        }
        __syncthreads();

#pragma unroll
        for (int ch = 0; ch < 2; ch++) {
            const float* KsC = Ks + ch * 64 * LDK;
            const float* VtC = Vt + ch * 64;

            // ---- scores: 16 q-rows x 64 kt per warp
            float s[8][4];
#pragma unroll
            for (int ng = 0; ng < 8; ng++) {
                s[ng][0] = 0.f; s[ng][1] = 0.f; s[ng][2] = 0.f; s[ng][3] = 0.f;
            }
            const int r0 = w * 16 + qa;
#pragma unroll
            for (int kk = 0; kk < 8; kk++) {
                float2 aA = *(float2*)&Qs[(r0)     * LDK + kk * 8 + 2 * cq];
                float2 aB = *(float2*)&Qs[(r0 + 8) * LDK + kk * 8 + 2 * cq];
                uint32_t a0 = __float_as_uint(aA.x), a1 = __float_as_uint(aB.x);
                uint32_t a2 = __float_as_uint(aA.y), a3 = __float_as_uint(aB.y);
#pragma unroll
                for (int ng = 0; ng < 8; ng++) {
                    float2 bv = *(float2*)&KsC[(ng * 8 + qa) * LDK + kk * 8 + 2 * cq];
                    mma_tf32(s[ng], a0, a1, a2, a3,
                             __float_as_uint(bv.x), __float_as_uint(bv.y));
                }
            }

            // ---- online softmax in registers (rows r0, r0+8)
            float mxa = -1e30f, mxb = -1e30f;
#pragma unroll
            for (int ng = 0; ng < 8; ng++) {
                mxa = fmaxf(mxa, fmaxf(s[ng][0], s[ng][1]));
                mxb = fmaxf(mxb, fmaxf(s[ng][2], s[ng][3]));
            }
            mxa = fmaxf(mxa, __shfl_xor_sync(0xffffffffu, mxa, 1));
            mxa = fmaxf(mxa, __shfl_xor_sync(0xffffffffu, mxa, 2));
            mxb = fmaxf(mxb, __shfl_xor_sync(0xffffffffu, mxb, 1));
            mxb = fmaxf(mxb, __shfl_xor_sync(0xffffffffu, mxb, 2));
            float mna = fmaxf(m_[0], mxa), mnb = fmaxf(m_[1], mxb);
            float suma = 0.f, sumb = 0.f;
#pragma unroll
            for (int ng = 0; ng < 8; ng++) {
                float p0 = to_tf32(__expf(s[ng][0] - mna));
                float p1 = to_tf32(__expf(s[ng][1] - mna));
                float p2 = to_tf32(__expf(s[ng][2] - mnb));
                float p3 = to_tf32(__expf(s[ng][3] - mnb));
                suma += p0 + p1;  sumb += p2 + p3;
                s[ng][0] = p0; s[ng][1] = p1; s[ng][2] = p2; s[ng][3] = p3;
            }
            suma += __shfl_xor_sync(0xffffffffu, suma, 1);
            suma += __shfl_xor_sync(0xffffffffu, suma, 2);
            sumb += __shfl_xor_sync(0xffffffffu, sumb, 1);
            sumb += __shfl_xor_sync(0xffffffffu, sumb, 2);
            float ala = __expf(m_[0] - mna), alb = __expf(m_[1] - mnb);
            m_[0] = mna; m_[1] = mnb;
            l_[0] = l_[0] * ala + suma;
            l_[1] = l_[1] * alb + sumb;
#pragma unroll
            for (int dg = 0; dg < 8; dg++) {
                o_[dg][0] *= ala; o_[dg][1] *= ala;
                o_[dg][2] *= alb; o_[dg][3] *= alb;
            }

            // ---- PV: O(16x64) += P(16x64) @ V(64x64); P straight from s regs
            // A slots: a0 = c0 (kt 2cq), a1 = c2, a2 = c1 (kt 2cq+1), a3 = c3
#pragma unroll
            for (int ng = 0; ng < 8; ng++) {
                uint32_t p0 = __float_as_uint(s[ng][0]), p1 = __float_as_uint(s[ng][1]);
                uint32_t p2 = __float_as_uint(s[ng][2]), p3 = __float_as_uint(s[ng][3]);
#pragma unroll
                for (int dg = 0; dg < 8; dg++) {
                    float2 bv = *(float2*)&VtC[(dg * 8 + qa) * LDKV + ng * 8 + 2 * cq];
                    mma_tf32(o_[dg], p0, p2, p1, p3,
                             __float_as_uint(bv.x), __float_as_uint(bv.y));
                }
            }
        }
    }

    // Final: O /= l, write [B,S,E] at column h*64
    {
        int b = bh >> 4, h = bh & 15;
        float inva = 1.0f / l_[0], invb = 1.0f / l_[1];
        int rowa = q0 + w * 16 + qa;
        int rowb = rowa + 8;
#pragma unroll
        for (int dg = 0; dg < 8; dg++) {
            int col = h * 64 + dg * 8 + 2 * cq;
            float2 va = make_float2(o_[dg][0] * inva, o_[dg][1] * inva);
            float2 vb = make_float2(o_[dg][2] * invb, o_[dg][3] * invb);
            *(float2*)&out[((size_t)b * SS + rowa) * EE + col] = va;
            *(float2*)&out[((size_t)b * SS + rowb) * EE + col] = vb;
        }
    }
}

// ---------------------------------------------------------------------------
extern "C" void kernel_launch(void* const* d_in, const int* in_sizes, int n_in,
                              void* d_out, int out_size)
{
    const float* query = (const float*)d_in[0];
    const float* key   = (const float*)d_in[1];
    const float* value = (const float*)d_in[2];
    const float* q_w   = (const float*)d_in[3];
    const float* q_b   = (const float*)d_in[4];
    const float* k_w   = (const float*)d_in[5];
    const float* k_b   = (const float*)d_in[6];
    const float* v_w   = (const float*)d_in[7];
    const float* v_b   = (const float*)d_in[8];
    const float* out_w = (const float*)d_in[9];
    const float* out_b = (const float*)d_in[10];
    float* out = (float*)d_out;

    float *gq, *gk, *gv, *gatt;
    cudaGetSymbolAddress((void**)&gq, g_q);
    cudaGetSymbolAddress((void**)&gk, g_k);
    cudaGetSymbolAddress((void**)&gv, g_v);
    cudaGetSymbolAddress((void**)&gatt, g_att);

    cudaFuncSetAttribute(proj_all, cudaFuncAttributeMaxDynamicSharedMemorySize, PROJ_SMEM);
    cudaFuncSetAttribute(attn_kernel, cudaFuncAttributeMaxDynamicSharedMemorySize, ATTN_SMEM);

    // Q/K/V projections in ONE launch (grid.z selects the set)
    dim3 pgrid3(EE / 128, MTOT / 128, 3);   // (8, 64, 3)
    proj_all<<<pgrid3, 256, PROJ_SMEM>>>(query, key, value,
                                         q_w, k_w, v_w,
                                         q_b, k_b, v_b,
                                         gq, gk, gv, 0);

    // Attention
    dim3 agrid(SS / 128, BB * HH);          // (16, 64)
    attn_kernel<<<agrid, 256, ATTN_SMEM>>>(gq, gk, gv, gatt);

    // Output projection
    dim3 pgrid1(EE / 128, MTOT / 128, 1);
    proj_all<<<pgrid1, 256, PROJ_SMEM>>>(gatt, gatt, gatt,
                                         out_w, out_w, out_w,
                                         out_b, out_b, out_b,
                                         out, out, out, 1);
}